// round 8
// baseline (speedup 1.0000x reference)
#include <cuda_runtime.h>

// LSTMModel: 2-layer LSTM (H=50), B=2048, T=512, input dim 1.
// Fused persistent kernel; one CTA per 16-batch tile.
// R6: thread (bg,j) owns gate column {j, j+50, j+100, j+150} -> nonlinearity in
// registers (no gates smem round-trip); double-buffered h state -> 2 barriers
// per timestep. Packed fma.rn.f32x2; conflict-free blocked W (BLK=20 pad).

#define Hh 50
#define G4 200
#define GP 224
#define BT 16           // batch tile per CTA
#define NT 224          // threads (4 b-groups x 56 j-slots)
#define TT 512
#define HCS 108         // hc row stride (mult of 4; 4*HCS mod 32 = 16 -> bg-straddle conflict-free)
#define H1OFF 52        // h1 starts at col 52 (h0: 0..49, pad 50..51)
#define NC0 13          // layer0 k-chunks (k 0..51, pad)
#define NC1 26          // layer1 k-chunks (k' 0..103: ih 0..49, pad 50..51, hh 52..101, pad)
#define BLK 20          // 16 data floats + 4 pad per (chunk, jslot) block

typedef unsigned long long ull;

#define SM_W0   0
#define SM_W1   (SM_W0 + NC0*56*BLK)      // 14560
#define SM_HC   (SM_W1 + NC1*56*BLK)      // +29120
#define SM_B0   (SM_HC + 2*BT*HCS)        // +3456
#define SM_B1   (SM_B0 + GP)
#define SM_WIH0 (SM_B1 + GP)
#define SM_FLOATS (SM_WIH0 + GP)
#define SMEM_BYTES (SM_FLOATS * sizeof(float))   // ~187 KB

__device__ __forceinline__ void ffma2(ull& d, ull a, ull b) {
    asm("fma.rn.f32x2 %0, %1, %2, %0;" : "+l"(d) : "l"(a), "l"(b));
}
__device__ __forceinline__ float psum(ull v) {
    float lo, hi;
    asm("mov.b64 {%0, %1}, %2;" : "=f"(lo), "=f"(hi) : "l"(v));
    return lo + hi;
}
__device__ __forceinline__ float sigf(float x) {
    float e = __expf(-x);
    return __fdividef(1.0f, 1.0f + e);
}
__device__ __forceinline__ float tanhf_fast(float x) {
    float e = __expf(2.0f * x);
    return 1.0f - __fdividef(2.0f, e + 1.0f);
}

__global__ __launch_bounds__(NT, 1)
void lstm2_kernel(const float* __restrict__ x,
                  const float* __restrict__ W_ih0, const float* __restrict__ W_hh0,
                  const float* __restrict__ b_ih0, const float* __restrict__ b_hh0,
                  const float* __restrict__ W_ih1, const float* __restrict__ W_hh1,
                  const float* __restrict__ b_ih1, const float* __restrict__ b_hh1,
                  const float* __restrict__ W_fc,  const float* __restrict__ b_fc,
                  float* __restrict__ out)
{
    extern __shared__ float sm[];
    float* W0    = sm + SM_W0;     // [NC0][56][BLK], block = gates {j,j+50,j+100,j+150} x 4k
    float* W1    = sm + SM_W1;     // [NC1][56][BLK]
    float* hcbuf = sm + SM_HC;     // 2 x [BT][HCS]
    float* bias0 = sm + SM_B0;
    float* bias1 = sm + SM_B1;
    float* wih0  = sm + SM_WIH0;

    const int tid = threadIdx.x;

    // ---- one-time fills ----
    for (int i = tid; i < NC0 * 56 * BLK; i += NT) {
        int blk = i / BLK, r = i - blk * BLK;
        int c = blk / 56, js = blk - c * 56;
        float v = 0.0f;
        if (r < 16 && js < 50) {
            int gg = r >> 2, kk = r & 3;
            int g = js + 50 * gg, k = 4 * c + kk;
            if (k < Hh) v = W_hh0[g * Hh + k];
        }
        W0[i] = v;
    }
    for (int i = tid; i < NC1 * 56 * BLK; i += NT) {
        int blk = i / BLK, r = i - blk * BLK;
        int c = blk / 56, js = blk - c * 56;
        float v = 0.0f;
        if (r < 16 && js < 50) {
            int gg = r >> 2, kk = r & 3;
            int g = js + 50 * gg, kp = 4 * c + kk;
            if (kp < 50) v = W_ih1[g * Hh + kp];
            else if (kp >= H1OFF && kp < H1OFF + Hh) v = W_hh1[g * Hh + (kp - H1OFF)];
        }
        W1[i] = v;
    }
    for (int g = tid; g < GP; g += NT) {
        bias0[g] = (g < G4) ? (b_ih0[g] + b_hh0[g]) : 0.0f;
        bias1[g] = (g < G4) ? (b_ih1[g] + b_hh1[g]) : 0.0f;
        wih0[g]  = (g < G4) ? W_ih0[g] : 0.0f;
    }
    for (int i = tid; i < 2 * BT * HCS; i += NT) hcbuf[i] = 0.0f;
    __syncthreads();

    // ---- thread identity: bg in 0..3 (4 b's each), js in 0..55 (gate column j) ----
    const int bg = tid / 56;
    const int js = tid - bg * 56;
    const int bbase = bg * 4;
    const bool active = (js < 50);

    float bi0[4], bi1[4], wiv[4];
    #pragma unroll
    for (int gg = 0; gg < 4; ++gg) {
        int g = js + 50 * gg;          // <= 205 < GP, zero-padded
        bi0[gg] = bias0[g];
        bi1[gg] = bias1[g];
        wiv[gg] = wih0[g];
    }

    float c0s[4] = {0.f, 0.f, 0.f, 0.f};
    float c1s[4] = {0.f, 0.f, 0.f, 0.f};

    float* cur  = hcbuf;               // h(t) written here
    float* prev = hcbuf + BT * HCS;    // h(t-1)

    const float* xrow = x + (size_t)(blockIdx.x) * BT * TT;
    const float* w0b = W0 + js * BLK;
    const float* w1b = W1 + js * BLK;

    const int row0 = (bbase + 0) * HCS;
    const int row1 = (bbase + 1) * HCS;
    const int row2 = (bbase + 2) * HCS;
    const int row3 = (bbase + 3) * HCS;

    for (int t = 0; t < TT; ++t) {
        // ===== layer 0: gates(i,f,g,o at col js) = bias + x*wih + h0(t-1) @ Whh0 =====
        ull a[4][4];
        #pragma unroll
        for (int bb = 0; bb < 4; ++bb)
            #pragma unroll
            for (int gg = 0; gg < 4; ++gg) a[bb][gg] = 0ull;

        #pragma unroll 2
        for (int c = 0; c < NC0; ++c) {
            const float* wb = w0b + c * (56 * BLK);
            ulonglong2 wq0 = *(const ulonglong2*)(wb + 0);
            ulonglong2 wq1 = *(const ulonglong2*)(wb + 4);
            ulonglong2 wq2 = *(const ulonglong2*)(wb + 8);
            ulonglong2 wq3 = *(const ulonglong2*)(wb + 12);
            int kc = 4 * c;
            ulonglong2 h0q = *(const ulonglong2*)(prev + row0 + kc);
            ulonglong2 h1q = *(const ulonglong2*)(prev + row1 + kc);
            ulonglong2 h2q = *(const ulonglong2*)(prev + row2 + kc);
            ulonglong2 h3q = *(const ulonglong2*)(prev + row3 + kc);
            ffma2(a[0][0], wq0.x, h0q.x); ffma2(a[0][0], wq0.y, h0q.y);
            ffma2(a[0][1], wq1.x, h0q.x); ffma2(a[0][1], wq1.y, h0q.y);
            ffma2(a[0][2], wq2.x, h0q.x); ffma2(a[0][2], wq2.y, h0q.y);
            ffma2(a[0][3], wq3.x, h0q.x); ffma2(a[0][3], wq3.y, h0q.y);
            ffma2(a[1][0], wq0.x, h1q.x); ffma2(a[1][0], wq0.y, h1q.y);
            ffma2(a[1][1], wq1.x, h1q.x); ffma2(a[1][1], wq1.y, h1q.y);
            ffma2(a[1][2], wq2.x, h1q.x); ffma2(a[1][2], wq2.y, h1q.y);
            ffma2(a[1][3], wq3.x, h1q.x); ffma2(a[1][3], wq3.y, h1q.y);
            ffma2(a[2][0], wq0.x, h2q.x); ffma2(a[2][0], wq0.y, h2q.y);
            ffma2(a[2][1], wq1.x, h2q.x); ffma2(a[2][1], wq1.y, h2q.y);
            ffma2(a[2][2], wq2.x, h2q.x); ffma2(a[2][2], wq2.y, h2q.y);
            ffma2(a[2][3], wq3.x, h2q.x); ffma2(a[2][3], wq3.y, h2q.y);
            ffma2(a[3][0], wq0.x, h3q.x); ffma2(a[3][0], wq0.y, h3q.y);
            ffma2(a[3][1], wq1.x, h3q.x); ffma2(a[3][1], wq1.y, h3q.y);
            ffma2(a[3][2], wq2.x, h3q.x); ffma2(a[3][2], wq2.y, h3q.y);
            ffma2(a[3][3], wq3.x, h3q.x); ffma2(a[3][3], wq3.y, h3q.y);
        }
        {
            float xv[4];
            xv[0] = __ldg(xrow + (bbase + 0) * TT + t);
            xv[1] = __ldg(xrow + (bbase + 1) * TT + t);
            xv[2] = __ldg(xrow + (bbase + 2) * TT + t);
            xv[3] = __ldg(xrow + (bbase + 3) * TT + t);
            #pragma unroll
            for (int bb = 0; bb < 4; ++bb) {
                float ri = fmaf(xv[bb], wiv[0], bi0[0]) + psum(a[bb][0]);
                float rf = fmaf(xv[bb], wiv[1], bi0[1]) + psum(a[bb][1]);
                float rg = fmaf(xv[bb], wiv[2], bi0[2]) + psum(a[bb][2]);
                float ro = fmaf(xv[bb], wiv[3], bi0[3]) + psum(a[bb][3]);
                float iv = sigf(ri), fv = sigf(rf);
                float gv = tanhf_fast(rg), ov = sigf(ro);
                float c = fmaf(fv, c0s[bb], iv * gv);
                c0s[bb] = c;
                if (active) cur[(bbase + bb) * HCS + js] = ov * tanhf_fast(c);
            }
        }
        __syncthreads();   // h0(t) visible to all

        // ===== layer 1: gates = bias + [h0(t); h1(t-1)] @ [Wih1; Whh1] =====
        ull b[4][4];
        #pragma unroll
        for (int bb = 0; bb < 4; ++bb)
            #pragma unroll
            for (int gg = 0; gg < 4; ++gg) b[bb][gg] = 0ull;

        #pragma unroll 2
        for (int c = 0; c < 13; ++c) {            // k' 0..51: h0(t) from cur
            const float* wb = w1b + c * (56 * BLK);
            ulonglong2 wq0 = *(const ulonglong2*)(wb + 0);
            ulonglong2 wq1 = *(const ulonglong2*)(wb + 4);
            ulonglong2 wq2 = *(const ulonglong2*)(wb + 8);
            ulonglong2 wq3 = *(const ulonglong2*)(wb + 12);
            int kc = 4 * c;
            ulonglong2 h0q = *(const ulonglong2*)(cur + row0 + kc);
            ulonglong2 h1q = *(const ulonglong2*)(cur + row1 + kc);
            ulonglong2 h2q = *(const ulonglong2*)(cur + row2 + kc);
            ulonglong2 h3q = *(const ulonglong2*)(cur + row3 + kc);
            ffma2(b[0][0], wq0.x, h0q.x); ffma2(b[0][0], wq0.y, h0q.y);
            ffma2(b[0][1], wq1.x, h0q.x); ffma2(b[0][1], wq1.y, h0q.y);
            ffma2(b[0][2], wq2.x, h0q.x); ffma2(b[0][2], wq2.y, h0q.y);
            ffma2(b[0][3], wq3.x, h0q.x); ffma2(b[0][3], wq3.y, h0q.y);
            ffma2(b[1][0], wq0.x, h1q.x); ffma2(b[1][0], wq0.y, h1q.y);
            ffma2(b[1][1], wq1.x, h1q.x); ffma2(b[1][1], wq1.y, h1q.y);
            ffma2(b[1][2], wq2.x, h1q.x); ffma2(b[1][2], wq2.y, h1q.y);
            ffma2(b[1][3], wq3.x, h1q.x); ffma2(b[1][3], wq3.y, h1q.y);
            ffma2(b[2][0], wq0.x, h2q.x); ffma2(b[2][0], wq0.y, h2q.y);
            ffma2(b[2][1], wq1.x, h2q.x); ffma2(b[2][1], wq1.y, h2q.y);
            ffma2(b[2][2], wq2.x, h2q.x); ffma2(b[2][2], wq2.y, h2q.y);
            ffma2(b[2][3], wq3.x, h2q.x); ffma2(b[2][3], wq3.y, h2q.y);
            ffma2(b[3][0], wq0.x, h3q.x); ffma2(b[3][0], wq0.y, h3q.y);
            ffma2(b[3][1], wq1.x, h3q.x); ffma2(b[3][1], wq1.y, h3q.y);
            ffma2(b[3][2], wq2.x, h3q.x); ffma2(b[3][2], wq2.y, h3q.y);
            ffma2(b[3][3], wq3.x, h3q.x); ffma2(b[3][3], wq3.y, h3q.y);
        }
        #pragma unroll 2
        for (int c = 13; c < NC1; ++c) {          // k' 52..103: h1(t-1) from prev
            const float* wb = w1b + c * (56 * BLK);
            ulonglong2 wq0 = *(const ulonglong2*)(wb + 0);
            ulonglong2 wq1 = *(const ulonglong2*)(wb + 4);
            ulonglong2 wq2 = *(const ulonglong2*)(wb + 8);
            ulonglong2 wq3 = *(const ulonglong2*)(wb + 12);
            int kc = 4 * c;
            ulonglong2 h0q = *(const ulonglong2*)(prev + row0 + kc);
            ulonglong2 h1q = *(const ulonglong2*)(prev + row1 + kc);
            ulonglong2 h2q = *(const ulonglong2*)(prev + row2 + kc);
            ulonglong2 h3q = *(const ulonglong2*)(prev + row3 + kc);
            ffma2(b[0][0], wq0.x, h0q.x); ffma2(b[0][0], wq0.y, h0q.y);
            ffma2(b[0][1], wq1.x, h0q.x); ffma2(b[0][1], wq1.y, h0q.y);
            ffma2(b[0][2], wq2.x, h0q.x); ffma2(b[0][2], wq2.y, h0q.y);
            ffma2(b[0][3], wq3.x, h0q.x); ffma2(b[0][3], wq3.y, h0q.y);
            ffma2(b[1][0], wq0.x, h1q.x); ffma2(b[1][0], wq0.y, h1q.y);
            ffma2(b[1][1], wq1.x, h1q.x); ffma2(b[1][1], wq1.y, h1q.y);
            ffma2(b[1][2], wq2.x, h1q.x); ffma2(b[1][2], wq2.y, h1q.y);
            ffma2(b[1][3], wq3.x, h1q.x); ffma2(b[1][3], wq3.y, h1q.y);
            ffma2(b[2][0], wq0.x, h2q.x); ffma2(b[2][0], wq0.y, h2q.y);
            ffma2(b[2][1], wq1.x, h2q.x); ffma2(b[2][1], wq1.y, h2q.y);
            ffma2(b[2][2], wq2.x, h2q.x); ffma2(b[2][2], wq2.y, h2q.y);
            ffma2(b[2][3], wq3.x, h2q.x); ffma2(b[2][3], wq3.y, h2q.y);
            ffma2(b[3][0], wq0.x, h3q.x); ffma2(b[3][0], wq0.y, h3q.y);
            ffma2(b[3][1], wq1.x, h3q.x); ffma2(b[3][1], wq1.y, h3q.y);
            ffma2(b[3][2], wq2.x, h3q.x); ffma2(b[3][2], wq2.y, h3q.y);
            ffma2(b[3][3], wq3.x, h3q.x); ffma2(b[3][3], wq3.y, h3q.y);
        }
        #pragma unroll
        for (int bb = 0; bb < 4; ++bb) {
            float ri = bi1[0] + psum(b[bb][0]);
            float rf = bi1[1] + psum(b[bb][1]);
            float rg = bi1[2] + psum(b[bb][2]);
            float ro = bi1[3] + psum(b[bb][3]);
            float iv = sigf(ri), fv = sigf(rf);
            float gv = tanhf_fast(rg), ov = sigf(ro);
            float c = fmaf(fv, c1s[bb], iv * gv);
            c1s[bb] = c;
            if (active) cur[(bbase + bb) * HCS + H1OFF + js] = ov * tanhf_fast(c);
        }
        __syncthreads();   // h(t) complete; swap

        float* tmp = cur; cur = prev; prev = tmp;
    }

    // ===== final FC: out[b] = h1(T-1)[b] . W_fc + b_fc  (final h in prev) =====
    if (tid < BT) {
        float s = b_fc[0];
        const float* hrow = prev + tid * HCS + H1OFF;
        #pragma unroll
        for (int j = 0; j < Hh; ++j) s = fmaf(hrow[j], __ldg(W_fc + j), s);
        out[blockIdx.x * BT + tid] = s;
    }
}

extern "C" void kernel_launch(void* const* d_in, const int* in_sizes, int n_in,
                              void* d_out, int out_size)
{
    const float* x     = (const float*)d_in[0];
    const float* W_ih0 = (const float*)d_in[1];
    const float* W_hh0 = (const float*)d_in[2];
    const float* b_ih0 = (const float*)d_in[3];
    const float* b_hh0 = (const float*)d_in[4];
    const float* W_ih1 = (const float*)d_in[5];
    const float* W_hh1 = (const float*)d_in[6];
    const float* b_ih1 = (const float*)d_in[7];
    const float* b_hh1 = (const float*)d_in[8];
    const float* W_fc  = (const float*)d_in[9];
    const float* b_fc  = (const float*)d_in[10];
    float* out = (float*)d_out;

    int B = in_sizes[0] / TT;          // x is [B, T, 1]
    int grid = B / BT;                 // 128 CTAs

    cudaFuncSetAttribute(lstm2_kernel, cudaFuncAttributeMaxDynamicSharedMemorySize, SMEM_BYTES);
    lstm2_kernel<<<grid, NT, SMEM_BYTES>>>(x, W_ih0, W_hh0, b_ih0, b_hh0,
                                           W_ih1, W_hh1, b_ih1, b_hh1,
                                           W_fc, b_fc, out);
}

// round 14
// speedup vs baseline: 1.0245x; 1.0245x over previous
#include <cuda_runtime.h>

// LSTMModel: 2-layer LSTM (H=50), B=2048, T=512, input dim 1.
// R9: 448 threads (14 warps) via k-split: lane pairs (kh=0/1) each take one
// k-pair of every 4k chunk; partials combined with shfl.xor(1). W crossbar
// traffic unchanged vs 224-thread version; occupancy doubled to hide LDS
// latency. Nonlinearity in registers; 2 barriers/step; packed fma.rn.f32x2.

#define Hh 50
#define G4 200
#define GP 224
#define BT 16           // batch tile per CTA
#define NT 448          // 4 bg x 112 slots (56 js x 2 kh)
#define NSL 112
#define TT 512
#define HCS 108         // hc row stride
#define H1OFF 52        // h1 at col 52 (h0 0..49, pad 50..51)
#define NC0 13          // layer0 k-chunks (k 0..51)
#define NC1 26          // layer1 k-chunks (k' 0..103)
#define BLK2 12         // 8 data floats + 4 pad per (chunk, slot) block
#define CHK (NSL*BLK2)  // 1344 floats per chunk

typedef unsigned long long ull;

#define SM_W0   0
#define SM_W1   (SM_W0 + NC0*CHK)        // 17472
#define SM_HC   (SM_W1 + NC1*CHK)        // +34944 = 52416
#define SM_B0   (SM_HC + 2*BT*HCS)       // +3456 = 55872
#define SM_B1   (SM_B0 + GP)
#define SM_WIH0 (SM_B1 + GP)
#define SM_FLOATS (SM_WIH0 + GP)         // 56544
#define SMEM_BYTES (SM_FLOATS * sizeof(float))   // 226176 B < 227 KB cap

__device__ __forceinline__ void ffma2(ull& d, ull a, ull b) {
    asm("fma.rn.f32x2 %0, %1, %2, %0;" : "+l"(d) : "l"(a), "l"(b));
}
__device__ __forceinline__ float psum(ull v) {
    float lo, hi;
    asm("mov.b64 {%0, %1}, %2;" : "=f"(lo), "=f"(hi) : "l"(v));
    return lo + hi;
}
__device__ __forceinline__ float sigf(float x) {
    float e = __expf(-x);
    return __fdividef(1.0f, 1.0f + e);
}
__device__ __forceinline__ float tanhf_fast(float x) {
    float e = __expf(2.0f * x);
    return 1.0f - __fdividef(2.0f, e + 1.0f);
}

__global__ __launch_bounds__(NT, 1)
void lstm2_kernel(const float* __restrict__ x,
                  const float* __restrict__ W_ih0, const float* __restrict__ W_hh0,
                  const float* __restrict__ b_ih0, const float* __restrict__ b_hh0,
                  const float* __restrict__ W_ih1, const float* __restrict__ W_hh1,
                  const float* __restrict__ b_ih1, const float* __restrict__ b_hh1,
                  const float* __restrict__ W_fc,  const float* __restrict__ b_fc,
                  float* __restrict__ out)
{
    extern __shared__ float sm[];
    float* W0    = sm + SM_W0;     // [NC0][NSL][BLK2]; block = 4 gates x 1 k-pair
    float* W1    = sm + SM_W1;     // [NC1][NSL][BLK2]
    float* hcbuf = sm + SM_HC;     // 2 x [BT][HCS]
    float* bias0 = sm + SM_B0;
    float* bias1 = sm + SM_B1;
    float* wih0  = sm + SM_WIH0;

    const int tid = threadIdx.x;

    // ---- one-time fills ----
    // W0 block (c, s=(js,kh)): floats r=0..7: gg=r>>1, kk=r&1, g=js+50*gg,
    // k = 4c + kh*2 + kk.  LDS.128 #1 = {g0 pair, g1 pair}, #2 = {g2, g3}.
    for (int i = tid; i < NC0 * CHK; i += NT) {
        int blk = i / BLK2, r = i - blk * BLK2;
        int c = blk / NSL, s = blk - c * NSL;
        int js = s >> 1, kh = s & 1;
        float v = 0.0f;
        if (r < 8 && js < 50) {
            int gg = r >> 1, kk = r & 1;
            int g = js + 50 * gg, k = 4 * c + kh * 2 + kk;
            if (k < Hh) v = W_hh0[g * Hh + k];
        }
        W0[i] = v;
    }
    for (int i = tid; i < NC1 * CHK; i += NT) {
        int blk = i / BLK2, r = i - blk * BLK2;
        int c = blk / NSL, s = blk - c * NSL;
        int js = s >> 1, kh = s & 1;
        float v = 0.0f;
        if (r < 8 && js < 50) {
            int gg = r >> 1, kk = r & 1;
            int g = js + 50 * gg, kp = 4 * c + kh * 2 + kk;
            if (kp < Hh) v = W_ih1[g * Hh + kp];
            else if (kp >= H1OFF && kp < H1OFF + Hh) v = W_hh1[g * Hh + (kp - H1OFF)];
        }
        W1[i] = v;
    }
    for (int g = tid; g < GP; g += NT) {
        bias0[g] = (g < G4) ? (b_ih0[g] + b_hh0[g]) : 0.0f;
        bias1[g] = (g < G4) ? (b_ih1[g] + b_hh1[g]) : 0.0f;
        wih0[g]  = (g < G4) ? W_ih0[g] : 0.0f;
    }
    for (int i = tid; i < 2 * BT * HCS; i += NT) hcbuf[i] = 0.0f;
    __syncthreads();

    // ---- identity: bg 0..3, s 0..111, js 0..55, kh 0..1 ----
    const int bg = tid / NSL;
    const int s  = tid - bg * NSL;
    const int js = s >> 1;
    const int kh = s & 1;
    const int kh2 = kh * 2;
    const int bbase = bg * 4;
    const bool active = (js < 50);

    float bi0[4], bi1[4], wiv[4];
    #pragma unroll
    for (int gg = 0; gg < 4; ++gg) {
        int g = js + 50 * gg;          // <= 205 < GP, zero-padded
        bi0[gg] = bias0[g];
        bi1[gg] = bias1[g];
        wiv[gg] = wih0[g];
    }

    // this lane owns nonlinearity for b = bbase + kh*2 + {0,1}
    const int bloc0 = kh2;             // 0 or 2
    float c0s[2] = {0.f, 0.f};
    float c1s[2] = {0.f, 0.f};

    float* cur  = hcbuf;
    float* prev = hcbuf + BT * HCS;

    const float* xrow = x + (size_t)(blockIdx.x) * BT * TT;
    const float* w0b = W0 + s * BLK2;
    const float* w1b = W1 + s * BLK2;

    const int row0 = (bbase + 0) * HCS;
    const int row1 = (bbase + 1) * HCS;
    const int row2 = (bbase + 2) * HCS;
    const int row3 = (bbase + 3) * HCS;

    for (int t = 0; t < TT; ++t) {
        // ===== layer 0 matmul (this lane: k-pair kh of every chunk) =====
        ull a[4][4];
        #pragma unroll
        for (int bb = 0; bb < 4; ++bb)
            #pragma unroll
            for (int gg = 0; gg < 4; ++gg) a[bb][gg] = 0ull;

        #pragma unroll 4
        for (int c = 0; c < NC0; ++c) {
            const float* wb = w0b + c * CHK;
            ulonglong2 wA = *(const ulonglong2*)(wb);      // g0, g1 k-pairs
            ulonglong2 wB = *(const ulonglong2*)(wb + 4);  // g2, g3
            int kc = 4 * c + kh2;
            ull h0 = *(const ull*)(prev + row0 + kc);
            ull h1 = *(const ull*)(prev + row1 + kc);
            ull h2 = *(const ull*)(prev + row2 + kc);
            ull h3 = *(const ull*)(prev + row3 + kc);
            ffma2(a[0][0], wA.x, h0); ffma2(a[0][1], wA.y, h0);
            ffma2(a[0][2], wB.x, h0); ffma2(a[0][3], wB.y, h0);
            ffma2(a[1][0], wA.x, h1); ffma2(a[1][1], wA.y, h1);
            ffma2(a[1][2], wB.x, h1); ffma2(a[1][3], wB.y, h1);
            ffma2(a[2][0], wA.x, h2); ffma2(a[2][1], wA.y, h2);
            ffma2(a[2][2], wB.x, h2); ffma2(a[2][3], wB.y, h2);
            ffma2(a[3][0], wA.x, h3); ffma2(a[3][1], wA.y, h3);
            ffma2(a[3][2], wB.x, h3); ffma2(a[3][3], wB.y, h3);
        }
        {
            // combine lane-pair partials: both lanes get full sums
            float pr[4][4];
            #pragma unroll
            for (int bb = 0; bb < 4; ++bb)
                #pragma unroll
                for (int gg = 0; gg < 4; ++gg) {
                    float p = psum(a[bb][gg]);
                    pr[bb][gg] = p + __shfl_xor_sync(0xffffffffu, p, 1);
                }
            // select the 2 b's this lane owns (kh ? b2,b3 : b0,b1)
            float s0i = kh ? pr[2][0] : pr[0][0];
            float s0f = kh ? pr[2][1] : pr[0][1];
            float s0g = kh ? pr[2][2] : pr[0][2];
            float s0o = kh ? pr[2][3] : pr[0][3];
            float s1i = kh ? pr[3][0] : pr[1][0];
            float s1f = kh ? pr[3][1] : pr[1][1];
            float s1g = kh ? pr[3][2] : pr[1][2];
            float s1o = kh ? pr[3][3] : pr[1][3];

            int b0 = bbase + bloc0, b1 = b0 + 1;
            float xv0 = __ldg(xrow + b0 * TT + t);
            float xv1 = __ldg(xrow + b1 * TT + t);

            float iv, fv, gv, ov, cc;
            iv = sigf(fmaf(xv0, wiv[0], bi0[0]) + s0i);
            fv = sigf(fmaf(xv0, wiv[1], bi0[1]) + s0f);
            gv = tanhf_fast(fmaf(xv0, wiv[2], bi0[2]) + s0g);
            ov = sigf(fmaf(xv0, wiv[3], bi0[3]) + s0o);
            cc = fmaf(fv, c0s[0], iv * gv); c0s[0] = cc;
            if (active) cur[b0 * HCS + js] = ov * tanhf_fast(cc);

            iv = sigf(fmaf(xv1, wiv[0], bi0[0]) + s1i);
            fv = sigf(fmaf(xv1, wiv[1], bi0[1]) + s1f);
            gv = tanhf_fast(fmaf(xv1, wiv[2], bi0[2]) + s1g);
            ov = sigf(fmaf(xv1, wiv[3], bi0[3]) + s1o);
            cc = fmaf(fv, c0s[1], iv * gv); c0s[1] = cc;
            if (active) cur[b1 * HCS + js] = ov * tanhf_fast(cc);
        }
        __syncthreads();   // h0(t) visible

        // ===== layer 1 matmul: [h0(t) from cur; h1(t-1) from prev] =====
        ull b[4][4];
        #pragma unroll
        for (int bb = 0; bb < 4; ++bb)
            #pragma unroll
            for (int gg = 0; gg < 4; ++gg) b[bb][gg] = 0ull;

        #pragma unroll 4
        for (int c = 0; c < 13; ++c) {             // k' 0..51 -> cur
            const float* wb = w1b + c * CHK;
            ulonglong2 wA = *(const ulonglong2*)(wb);
            ulonglong2 wB = *(const ulonglong2*)(wb + 4);
            int kc = 4 * c + kh2;
            ull h0 = *(const ull*)(cur + row0 + kc);
            ull h1 = *(const ull*)(cur + row1 + kc);
            ull h2 = *(const ull*)(cur + row2 + kc);
            ull h3 = *(const ull*)(cur + row3 + kc);
            ffma2(b[0][0], wA.x, h0); ffma2(b[0][1], wA.y, h0);
            ffma2(b[0][2], wB.x, h0); ffma2(b[0][3], wB.y, h0);
            ffma2(b[1][0], wA.x, h1); ffma2(b[1][1], wA.y, h1);
            ffma2(b[1][2], wB.x, h1); ffma2(b[1][3], wB.y, h1);
            ffma2(b[2][0], wA.x, h2); ffma2(b[2][1], wA.y, h2);
            ffma2(b[2][2], wB.x, h2); ffma2(b[2][3], wB.y, h2);
            ffma2(b[3][0], wA.x, h3); ffma2(b[3][1], wA.y, h3);
            ffma2(b[3][2], wB.x, h3); ffma2(b[3][3], wB.y, h3);
        }
        #pragma unroll 4
        for (int c = 13; c < NC1; ++c) {           // k' 52..103 -> prev
            const float* wb = w1b + c * CHK;
            ulonglong2 wA = *(const ulonglong2*)(wb);
            ulonglong2 wB = *(const ulonglong2*)(wb + 4);
            int kc = 4 * c + kh2;
            ull h0 = *(const ull*)(prev + row0 + kc);
            ull h1 = *(const ull*)(prev + row1 + kc);
            ull h2 = *(const ull*)(prev + row2 + kc);
            ull h3 = *(const ull*)(prev + row3 + kc);
            ffma2(b[0][0], wA.x, h0); ffma2(b[0][1], wA.y, h0);
            ffma2(b[0][2], wB.x, h0); ffma2(b[0][3], wB.y, h0);
            ffma2(b[1][0], wA.x, h1); ffma2(b[1][1], wA.y, h1);
            ffma2(b[1][2], wB.x, h1); ffma2(b[1][3], wB.y, h1);
            ffma2(b[2][0], wA.x, h2); ffma2(b[2][1], wA.y, h2);
            ffma2(b[2][2], wB.x, h2); ffma2(b[2][3], wB.y, h2);
            ffma2(b[3][0], wA.x, h3); ffma2(b[3][1], wA.y, h3);
            ffma2(b[3][2], wB.x, h3); ffma2(b[3][3], wB.y, h3);
        }
        {
            float pr[4][4];
            #pragma unroll
            for (int bb = 0; bb < 4; ++bb)
                #pragma unroll
                for (int gg = 0; gg < 4; ++gg) {
                    float p = psum(b[bb][gg]);
                    pr[bb][gg] = p + __shfl_xor_sync(0xffffffffu, p, 1);
                }
            float s0i = kh ? pr[2][0] : pr[0][0];
            float s0f = kh ? pr[2][1] : pr[0][1];
            float s0g = kh ? pr[2][2] : pr[0][2];
            float s0o = kh ? pr[2][3] : pr[0][3];
            float s1i = kh ? pr[3][0] : pr[1][0];
            float s1f = kh ? pr[3][1] : pr[1][1];
            float s1g = kh ? pr[3][2] : pr[1][2];
            float s1o = kh ? pr[3][3] : pr[1][3];

            int b0 = bbase + bloc0, b1 = b0 + 1;

            float iv, fv, gv, ov, cc;
            iv = sigf(bi1[0] + s0i);
            fv = sigf(bi1[1] + s0f);
            gv = tanhf_fast(bi1[2] + s0g);
            ov = sigf(bi1[3] + s0o);
            cc = fmaf(fv, c1s[0], iv * gv); c1s[0] = cc;
            if (active) cur[b0 * HCS + H1OFF + js] = ov * tanhf_fast(cc);

            iv = sigf(bi1[0] + s1i);
            fv = sigf(bi1[1] + s1f);
            gv = tanhf_fast(bi1[2] + s1g);
            ov = sigf(bi1[3] + s1o);
            cc = fmaf(fv, c1s[1], iv * gv); c1s[1] = cc;
            if (active) cur[b1 * HCS + H1OFF + js] = ov * tanhf_fast(cc);
        }
        __syncthreads();

        float* tmp = cur; cur = prev; prev = tmp;
    }

    // ===== final FC: out[b] = h1(T-1)[b] . W_fc + b_fc  (final h in prev) =====
    if (tid < BT) {
        float ssum = b_fc[0];
        const float* hrow = prev + tid * HCS + H1OFF;
        #pragma unroll
        for (int j = 0; j < Hh; ++j) ssum = fmaf(hrow[j], __ldg(W_fc + j), ssum);
        out[blockIdx.x * BT + tid] = ssum;
    }
}

extern "C" void kernel_launch(void* const* d_in, const int* in_sizes, int n_in,
                              void* d_out, int out_size)
{
    const float* x     = (const float*)d_in[0];
    const float* W_ih0 = (const float*)d_in[1];
    const float* W_hh0 = (const float*)d_in[2];
    const float* b_ih0 = (const float*)d_in[3];
    const float* b_hh0 = (const float*)d_in[4];
    const float* W_ih1 = (const float*)d_in[5];
    const float* W_hh1 = (const float*)d_in[6];
    const float* b_ih1 = (const float*)d_in[7];
    const float* b_hh1 = (const float*)d_in[8];
    const float* W_fc  = (const float*)d_in[9];
    const float* b_fc  = (const float*)d_in[10];
    float* out = (float*)d_out;

    int B = in_sizes[0] / TT;          // x is [B, T, 1]
    int grid = B / BT;                 // 128 CTAs

    cudaFuncSetAttribute(lstm2_kernel, cudaFuncAttributeMaxDynamicSharedMemorySize, SMEM_BYTES);
    lstm2_kernel<<<grid, NT, SMEM_BYTES>>>(x, W_ih0, W_hh0, b_ih0, b_hh0,
                                           W_ih1, W_hh1, b_ih1, b_hh1,
                                           W_fc, b_fc, out);
}